// round 10
// baseline (speedup 1.0000x reference)
#include <cuda_runtime.h>
#include <cuda_bf16.h>

// Fixed problem constants:
//   SIGMA=8 -> 1/(2*sigma^2)=1/128, C_SIZE=512, STRIDE=8 -> 64x64 grid,
//   cood[k]=8k+4, B=16, N=512, BG_RATIO=0.15, EPS=1e-5
//   out[b, p, i*64+j], p in [0,512], fp32, [16, 513, 4096]

#define CGRID   64
#define NPTS    512
#define PCHUNK  32
#define NCHUNK  (NPTS / PCHUNK)     // 16
#define BFIX    16
#define MPIX    (CGRID * CGRID)     // 4096
#define KINV    (1.0f / 128.0f)
#define PGRP    8

// Per-image block group: [64 partial | 4 combine | 64 write] = 132 blocks.
// Image-major interleaving => writes of image b overlap partials of b+1..
#define GP      64
#define GC      4
#define GW      64
#define GRP     (GP + GC + GW)      // 132
#define NBLOCKS (BFIX * GRP)        // 2112

// Static scratch (no runtime allocation allowed)
__device__ float g_psum[BFIX * NCHUNK * MPIX];   // 4 MB per-chunk partial sums
__device__ float g_pmax[BFIX * NCHUNK * MPIX];   // 4 MB per-chunk max products
__device__ float g_invt[BFIX * MPIX];            // 1/denominator per pixel
__device__ int   g_pdone[BFIX];                  // partial blocks retired
__device__ int   g_cdone[BFIX];                  // combine blocks retired
__device__ int   g_wdone[BFIX];                  // write blocks retired

// Acquire: tid0 spins until *ctr >= target, then block-wide acquire.
__device__ __forceinline__ void spin_acquire(int* ctr, int target)
{
    if (threadIdx.x == 0) {
        while (atomicAdd(ctr, 0) < target) __nanosleep(128);
        __threadfence();
    }
    __syncthreads();
}

// Release: all threads' prior stores visible, then tid0 bumps counter.
__device__ __forceinline__ int release_add(int* ctr)
{
    __threadfence();
    __syncthreads();
    int r = -1;
    if (threadIdx.x == 0) r = atomicAdd(ctr, 1);
    return r;
}

__global__ __launch_bounds__(256)
void k_fused(const float* __restrict__ points,
             const float* __restrict__ st_sizes,
             float* __restrict__ out)
{
    const int b    = blockIdx.x / GRP;     // image (image-major groups)
    const int role = blockIdx.x % GRP;
    const int tid  = threadIdx.x;

    __shared__ float sm[PCHUNK * CGRID + 16 * PCHUNK + 2 * PCHUNK]; // 10.5 KB

    if (role < GP) {
        // ================= PARTIAL role: (chunk, 16-row tile) ===============
        const int c  = role >> 2;           // chunk 0..15
        const int i0 = (role & 3) * 16;     // i-tile base
        const int ti = tid >> 4;
        const int jg = tid & 15;

        float2* pts_s = (float2*)sm;                         // 32 float2
        float*  Ex_s  = sm + 2 * PCHUNK;                     // 2048
        float*  Ey_s  = Ex_s + PCHUNK * CGRID;               // 512

        const float2* ptb = (const float2*)points + b * NPTS + c * PCHUNK;
        if (tid < PCHUNK) pts_s[tid] = ptb[tid];
        __syncthreads();

        #pragma unroll
        for (int k = 0; k < (PCHUNK * CGRID) / 256; ++k) {   // 8 iters
            int idx = tid + k * 256;
            int p = idx >> 6, jj = idx & 63;
            float dx = pts_s[p].x - (float)(jj * 8 + 4);
            Ex_s[idx] = __expf(-dx * dx * KINV);
        }
        #pragma unroll
        for (int k = 0; k < (16 * PCHUNK) / 256; ++k) {      // 2 iters
            int idx = tid + k * 256;
            int ii = idx >> 5, p = idx & (PCHUNK - 1);
            float dy = pts_s[p].y - (float)((i0 + ii) * 8 + 4);
            Ey_s[idx] = __expf(-dy * dy * KINV);
        }
        __syncthreads();

        float4 sum = make_float4(0.f, 0.f, 0.f, 0.f);
        float4 mx  = make_float4(0.f, 0.f, 0.f, 0.f);
        const float4* Ex4 = (const float4*)Ex_s;

        #pragma unroll 8
        for (int p = 0; p < PCHUNK; ++p) {
            float  ey = Ey_s[ti * PCHUNK + p];
            float4 ex = Ex4[p * 16 + jg];
            float p0 = ey * ex.x;
            float p1 = ey * ex.y;
            float p2 = ey * ex.z;
            float p3 = ey * ex.w;
            sum.x += p0; sum.y += p1; sum.z += p2; sum.w += p3;
            mx.x = fmaxf(mx.x, p0); mx.y = fmaxf(mx.y, p1);
            mx.z = fmaxf(mx.z, p2); mx.w = fmaxf(mx.w, p3);
        }

        int o = (b * NCHUNK + c) * MPIX + (i0 + ti) * CGRID + jg * 4;
        *(float4*)(g_psum + o) = sum;
        *(float4*)(g_pmax + o) = mx;

        release_add(&g_pdone[b]);
    }
    else if (role < GP + GC) {
        // ================= COMBINE role: quarter of pixels ==================
        const int q = role - GP;
        const int r = q * 256 + tid;         // float4 index within image

        spin_acquire(&g_pdone[b], GP);       // all partials of image b done

        const float4* ps = (const float4*)g_psum;
        const float4* pm = (const float4*)g_pmax;
        int base = b * NCHUNK * 1024 + r;

        float4 sum = make_float4(0.f, 0.f, 0.f, 0.f);
        float4 mx  = make_float4(0.f, 0.f, 0.f, 0.f);
        #pragma unroll
        for (int c = 0; c < NCHUNK; ++c) {
            float4 s = ps[base + c * 1024];
            float4 m = pm[base + c * 1024];
            sum.x += s.x; sum.y += s.y; sum.z += s.z; sum.w += s.w;
            mx.x = fmaxf(mx.x, m.x); mx.y = fmaxf(mx.y, m.y);
            mx.z = fmaxf(mx.z, m.z); mx.w = fmaxf(mx.w, m.w);
        }

        float sc = st_sizes[b] * 0.15f;
        float ss = sc * sc;
        float4 invt, bgp;
        {
            float mind = -128.0f * __logf(fmaxf(mx.x, 1e-38f));
            float ebg = __expf(-(ss / (mind + 1e-5f)) * KINV);
            float iv = 1.0f / (sum.x + ebg); invt.x = iv; bgp.x = ebg * iv;
        }
        {
            float mind = -128.0f * __logf(fmaxf(mx.y, 1e-38f));
            float ebg = __expf(-(ss / (mind + 1e-5f)) * KINV);
            float iv = 1.0f / (sum.y + ebg); invt.y = iv; bgp.y = ebg * iv;
        }
        {
            float mind = -128.0f * __logf(fmaxf(mx.z, 1e-38f));
            float ebg = __expf(-(ss / (mind + 1e-5f)) * KINV);
            float iv = 1.0f / (sum.z + ebg); invt.z = iv; bgp.z = ebg * iv;
        }
        {
            float mind = -128.0f * __logf(fmaxf(mx.w, 1e-38f));
            float ebg = __expf(-(ss / (mind + 1e-5f)) * KINV);
            float iv = 1.0f / (sum.w + ebg); invt.w = iv; bgp.w = ebg * iv;
        }

        ((float4*)g_invt)[b * 1024 + r] = invt;
        __stcs(((float4*)out) + (b * 513 + 512) * 1024 + r, bgp);

        release_add(&g_cdone[b]);
    }
    else {
        // ================= WRITE role: group of 8 planes ====================
        const int pg = role - GP - GC;       // 0..63

        float (*Ex_s)[CGRID] = (float (*)[CGRID])sm;            // [8][64]
        float (*Ey_s)[CGRID] = (float (*)[CGRID])(sm + PGRP * CGRID);

        // Fill per-plane Ex/Ey rows (independent of partial/combine data).
        #pragma unroll
        for (int k = 0; k < 4; ++k) {
            int ii   = tid + k * 256;           // 0..1023
            int pl   = ii >> 7;
            int rest = ii & 127;
            int t    = rest >> 6;               // 0: Ex (x), 1: Ey (y)
            int cell = rest & 63;
            int p    = pg * PGRP + pl;
            float coord = points[(b * NPTS + p) * 2 + t];
            float d = coord - (float)(cell * 8 + 4);
            float e = __expf(-d * d * KINV);
            if (t) Ey_s[pl][cell] = e; else Ex_s[pl][cell] = e;
        }

        spin_acquire(&g_cdone[b], GC);          // invt of image b ready
        // (spin_acquire ends in __syncthreads -> smem fill also synced)

        float4 invt[4];
        #pragma unroll
        for (int k = 0; k < 4; ++k)
            invt[k] = ((const float4*)g_invt)[b * 1024 + tid + k * 256];

        float4* op = (float4*)out + ((size_t)b * 513 + pg * PGRP) * 1024;

        #pragma unroll
        for (int pl = 0; pl < PGRP; ++pl) {
            const float4* Ex4 = (const float4*)Ex_s[pl];
            #pragma unroll
            for (int k = 0; k < 4; ++k) {
                int f  = tid + k * 256;
                int i  = f >> 4;
                int jg = f & 15;
                float  ey = Ey_s[pl][i];
                float4 ex = Ex4[jg];
                float4 v;
                v.x = (ey * ex.x) * invt[k].x;
                v.y = (ey * ex.y) * invt[k].y;
                v.z = (ey * ex.z) * invt[k].z;
                v.w = (ey * ex.w) * invt[k].w;
                __stcs(op + (size_t)pl * 1024 + f, v);
            }
        }

        // Last write block of image b resets its counters for the next replay.
        int r = release_add(&g_wdone[b]);
        if (threadIdx.x == 0 && r == GW - 1) {
            atomicExch(&g_pdone[b], 0);
            atomicExch(&g_cdone[b], 0);
            atomicExch(&g_wdone[b], 0);
        }
    }
}

// ---------------------------------------------------------------------------
extern "C" void kernel_launch(void* const* d_in, const int* in_sizes, int n_in,
                              void* d_out, int out_size)
{
    const float* points   = (const float*)d_in[0];   // [16, 512, 2]
    const float* st_sizes = (const float*)d_in[1];   // [16]
    float* out = (float*)d_out;                      // [16, 513, 4096]

    k_fused<<<NBLOCKS, 256>>>(points, st_sizes, out);
}

// round 11
// speedup vs baseline: 1.9316x; 1.9316x over previous
#include <cuda_runtime.h>
#include <cuda_bf16.h>

// Fixed problem constants:
//   SIGMA=8 -> 1/(2*sigma^2)=1/128, C_SIZE=512, STRIDE=8 -> 64x64 grid,
//   cood[k]=8k+4, B=16, N=512, BG_RATIO=0.15, EPS=1e-5
//   out[b, p, i*64+j], p in [0,512], fp32, [16, 513, 4096]

#define CGRID   64
#define NPTS    512
#define PCHUNK  32
#define NCHUNK  (NPTS / PCHUNK)     // 16
#define BFIX    16
#define MPIX    (CGRID * CGRID)     // 4096
#define KINV    (1.0f / 128.0f)

// Static scratch (no runtime allocation allowed)
__device__ float g_psum[BFIX * NCHUNK * MPIX];   // 4 MB per-chunk partial sums
__device__ float g_pmax[BFIX * NCHUNK * MPIX];   // 4 MB per-chunk max products
__device__ float g_invt[BFIX * MPIX];            // 1/denominator per pixel

// ---------------------------------------------------------------------------
// K1: per (b, chunk, 16-row tile): partial exp-sum + max product (smem tables).
//     min-distance recovered later as -128*ln(max product).
// ---------------------------------------------------------------------------
__global__ __launch_bounds__(256)
void k_partial(const float* __restrict__ points)
{
    const int b   = blockIdx.z;
    const int c   = blockIdx.y;
    const int i0  = blockIdx.x * 16;
    const int tid = threadIdx.x;
    const int ti  = tid >> 4;      // 0..15 row in tile
    const int jg  = tid & 15;      // owns j = jg*4 + {0..3}

    __shared__ float2 pts_s[PCHUNK];            // 256 B
    __shared__ float  Ex_s[PCHUNK * CGRID];     // 8 KB  [p][j]
    __shared__ float  Ey_s[16 * PCHUNK];        // 2 KB  [ti][p]

    const float2* ptb = (const float2*)points + b * NPTS + c * PCHUNK;
    if (tid < PCHUNK) pts_s[tid] = ptb[tid];
    __syncthreads();

    #pragma unroll
    for (int k = 0; k < (PCHUNK * CGRID) / 256; ++k) {   // 8 iters
        int idx = tid + k * 256;
        int p = idx >> 6, jj = idx & 63;
        float dx = pts_s[p].x - (float)(jj * 8 + 4);
        Ex_s[idx] = __expf(-dx * dx * KINV);
    }
    #pragma unroll
    for (int k = 0; k < (16 * PCHUNK) / 256; ++k) {      // 2 iters
        int idx = tid + k * 256;
        int ii = idx >> 5, p = idx & (PCHUNK - 1);
        float dy = pts_s[p].y - (float)((i0 + ii) * 8 + 4);
        Ey_s[idx] = __expf(-dy * dy * KINV);
    }
    __syncthreads();

    float4 sum = make_float4(0.f, 0.f, 0.f, 0.f);
    float4 mx  = make_float4(0.f, 0.f, 0.f, 0.f);
    const float4* Ex4 = (const float4*)Ex_s;

    #pragma unroll 8
    for (int p = 0; p < PCHUNK; ++p) {
        float  ey = Ey_s[ti * PCHUNK + p];
        float4 ex = Ex4[p * 16 + jg];
        float p0 = ey * ex.x;
        float p1 = ey * ex.y;
        float p2 = ey * ex.z;
        float p3 = ey * ex.w;
        sum.x += p0; sum.y += p1; sum.z += p2; sum.w += p3;
        mx.x = fmaxf(mx.x, p0); mx.y = fmaxf(mx.y, p1);
        mx.z = fmaxf(mx.z, p2); mx.w = fmaxf(mx.w, p3);
    }

    int o = (b * NCHUNK + c) * MPIX + (i0 + ti) * CGRID + jg * 4;
    *(float4*)(g_psum + o) = sum;
    *(float4*)(g_pmax + o) = mx;
}

// ---------------------------------------------------------------------------
// K2: reduce chunk partials -> invt per pixel; write background plane p=512.
// ---------------------------------------------------------------------------
__global__ __launch_bounds__(256)
void k_combine(const float* __restrict__ st_sizes, float* __restrict__ out)
{
    int idx = blockIdx.x * 256 + threadIdx.x;       // over BFIX*MPIX/4 = 16384
    int b = idx >> 10;                               // MPIX/4 = 1024
    int r = idx & 1023;

    const float4* ps = (const float4*)g_psum;
    const float4* pm = (const float4*)g_pmax;
    int base = b * NCHUNK * 1024 + r;

    float4 sum = make_float4(0.f, 0.f, 0.f, 0.f);
    float4 mx  = make_float4(0.f, 0.f, 0.f, 0.f);
    #pragma unroll
    for (int c = 0; c < NCHUNK; ++c) {
        float4 s = ps[base + c * 1024];
        float4 m = pm[base + c * 1024];
        sum.x += s.x; sum.y += s.y; sum.z += s.z; sum.w += s.w;
        mx.x = fmaxf(mx.x, m.x); mx.y = fmaxf(mx.y, m.y);
        mx.z = fmaxf(mx.z, m.z); mx.w = fmaxf(mx.w, m.w);
    }

    float sc = st_sizes[b] * 0.15f;
    float ss = sc * sc;
    float4 invt, bgp;
    {
        float mind = -128.0f * __logf(fmaxf(mx.x, 1e-38f));
        float ebg = __expf(-(ss / (mind + 1e-5f)) * KINV);
        float iv = 1.0f / (sum.x + ebg); invt.x = iv; bgp.x = ebg * iv;
    }
    {
        float mind = -128.0f * __logf(fmaxf(mx.y, 1e-38f));
        float ebg = __expf(-(ss / (mind + 1e-5f)) * KINV);
        float iv = 1.0f / (sum.y + ebg); invt.y = iv; bgp.y = ebg * iv;
    }
    {
        float mind = -128.0f * __logf(fmaxf(mx.z, 1e-38f));
        float ebg = __expf(-(ss / (mind + 1e-5f)) * KINV);
        float iv = 1.0f / (sum.z + ebg); invt.z = iv; bgp.z = ebg * iv;
    }
    {
        float mind = -128.0f * __logf(fmaxf(mx.w, 1e-38f));
        float ebg = __expf(-(ss / (mind + 1e-5f)) * KINV);
        float iv = 1.0f / (sum.w + ebg); invt.w = iv; bgp.w = ebg * iv;
    }

    ((float4*)g_invt)[b * 1024 + r] = invt;
    __stwt(((float4*)out) + (b * 513 + 512) * 1024 + r, bgp);  // background plane
}

// ---------------------------------------------------------------------------
// K3: normalized writes. Block = (b, group of 8 planes) -> fully contiguous
//     128 KB output span per block. WRITE-THROUGH stores (no L2 allocate
//     churn) — the untested point in the store-policy space; cs and wb both
//     left every memory unit below 60% busy.
// ---------------------------------------------------------------------------
#define PGRP 8

__global__ __launch_bounds__(256)
void k_write(const float* __restrict__ points, float* __restrict__ out)
{
    const int b   = blockIdx.x >> 6;            // 0..15
    const int pg  = blockIdx.x & 63;            // plane group: p = pg*8 + pl
    const int tid = threadIdx.x;

    __shared__ float Ex_s[PGRP][CGRID];         // 2 KB
    __shared__ float Ey_s[PGRP][CGRID];         // 2 KB

    // Fill per-plane Ex/Ey rows: 8 planes * 64 cells * 2 tables = 1024 exps.
    #pragma unroll
    for (int k = 0; k < 4; ++k) {
        int idx  = tid + k * 256;               // 0..1023
        int pl   = idx >> 7;
        int rest = idx & 127;
        int t    = rest >> 6;                   // 0: Ex (x), 1: Ey (y)
        int cell = rest & 63;
        int p    = pg * PGRP + pl;
        float coord = points[(b * NPTS + p) * 2 + t];
        float d = coord - (float)(cell * 8 + 4);
        float e = __expf(-d * d * KINV);
        if (t) Ey_s[pl][cell] = e; else Ex_s[pl][cell] = e;
    }

    // invt for this image: each thread holds 4 float4 (covers its 4 f-slots).
    const float4* iv4 = (const float4*)g_invt + b * 1024;
    float4 invt[4];
    #pragma unroll
    for (int k = 0; k < 4; ++k)
        invt[k] = __ldg(iv4 + tid + k * 256);

    __syncthreads();

    float4* op = (float4*)out + ((size_t)b * 513 + pg * PGRP) * 1024;

    #pragma unroll
    for (int pl = 0; pl < PGRP; ++pl) {
        const float4* Ex4 = (const float4*)Ex_s[pl];
        #pragma unroll
        for (int k = 0; k < 4; ++k) {
            int f  = tid + k * 256;             // float4 index within plane
            int i  = f >> 4;
            int jg = f & 15;
            float  ey = Ey_s[pl][i];
            float4 ex = Ex4[jg];
            float4 v;
            v.x = (ey * ex.x) * invt[k].x;
            v.y = (ey * ex.y) * invt[k].y;
            v.z = (ey * ex.z) * invt[k].z;
            v.w = (ey * ex.w) * invt[k].w;
            __stwt(op + (size_t)pl * 1024 + f, v);
        }
    }
}

// ---------------------------------------------------------------------------
extern "C" void kernel_launch(void* const* d_in, const int* in_sizes, int n_in,
                              void* d_out, int out_size)
{
    const float* points   = (const float*)d_in[0];   // [16, 512, 2]
    const float* st_sizes = (const float*)d_in[1];   // [16]
    float* out = (float*)d_out;                      // [16, 513, 4096]

    dim3 g1(CGRID / 16, NCHUNK, BFIX);               // (4, 16, 16) = 1024 blocks
    k_partial<<<g1, 256>>>(points);
    k_combine<<<(BFIX * MPIX / 4) / 256, 256>>>(st_sizes, out);
    k_write<<<BFIX * (NPTS / PGRP), 256>>>(points, out);   // 1024 blocks
}